// round 14
// baseline (speedup 1.0000x reference)
#include <cuda_runtime.h>
#include <cuda_bf16.h>

// out[b,t,v] = sum_d x[b,t,d,v] * w[d] + bias
// x: (2, 512, 8, 32000) fp32 contiguous; w: (8,); b: (1,)
// out: (2, 512, 32000) fp32
//
// HBM-roofline kernel (~90% sustained DRAM, 7.13 TB/s, 164.4 us best).
// R13: final block-size axis point — 128-thread blocks (64000 one-shot
// blocks). Identical per-thread pattern to the converged best:
//   1 float4/thread, 8 front-batched loads (MLP=8), __ldcs/__stcs,
//   exact grid (64000*128 == 8,192,000), dense rasterized ordering.
// Measured so far: 256 best (90.0-90.3% DRAM), 512 -0.5%, persistent
// grid -5%, 2x float4/thread -0.7%.

#define DEPTH   8
#define VROW4   8000                    // 32000 floats / 4 per (b,t,d) row
#define NTHREADS 128

__global__ __launch_bounds__(NTHREADS) void ttm_kernel(
    const float4* __restrict__ x,
    const float*  __restrict__ w,
    const float*  __restrict__ bias,
    float4* __restrict__ out)
{
    long i = (long)blockIdx.x * NTHREADS + threadIdx.x;  // exact: no bounds check

    int row = (int)(i / VROW4);   // which (b,t) of 1024
    int v4  = (int)(i % VROW4);

    // weights: tiny, L1/L2-broadcast; registers for the whole kernel
    float wr[DEPTH];
#pragma unroll
    for (int d = 0; d < DEPTH; ++d) wr[d] = __ldg(&w[d]);
    const float bb = __ldg(bias);

    const float4* p = x + (long)row * DEPTH * VROW4 + v4;

    // Front-batch all 8 independent streaming loads (MLP=8)
    float4 t[DEPTH];
#pragma unroll
    for (int d = 0; d < DEPTH; ++d)
        t[d] = __ldcs(p + (long)d * VROW4);          // evict-first: zero reuse

    float4 acc;
    acc.x = bb; acc.y = bb; acc.z = bb; acc.w = bb;

#pragma unroll
    for (int d = 0; d < DEPTH; ++d) {
        acc.x = fmaf(t[d].x, wr[d], acc.x);
        acc.y = fmaf(t[d].y, wr[d], acc.y);
        acc.z = fmaf(t[d].z, wr[d], acc.z);
        acc.w = fmaf(t[d].w, wr[d], acc.w);
    }

    __stcs(&out[i], acc);                            // streaming store
}

extern "C" void kernel_launch(void* const* d_in, const int* in_sizes, int n_in,
                              void* d_out, int out_size)
{
    const float4* x    = (const float4*)d_in[0];
    const float*  w    = (const float*) d_in[1];
    const float*  bias = (const float*) d_in[2];
    float4*       out  = (float4*)      d_out;

    ttm_kernel<<<64000, NTHREADS>>>(x, w, bias, out);
}